// round 17
// baseline (speedup 1.0000x reference)
#include <cuda_runtime.h>

// SSM via truncated impulse response (L=24):
//   y[b,f,t] = sum_{tau<L} k[f,tau] x[b,f,t-tau],  k[f,tau] = C A_bar^tau B_bar
//   A_bar = 2(I-A/2)^{-1} - I,  B_bar = 0.5(A_bar+I)B.
// Phase1 now 512 threads/CTA (ONE row per thread) to double warp parallelism
//   (R12 profile: occ 21%, issue 26% => latency-bound, needs warps):
//   block-2 in-place GJ, contiguous cols, pivot pair exchanged via shfl_xor 8
//   (rows 2s,2s+1 are 8 lanes apart in one warp), 1 barrier/stage. Then two
//   concurrent 128-thread chains (a[32]); k_tau = w_i . u_{tau-i}.
// Phase2: proven FIR (L=24) + PDL overlap.

#define NF 256
#define TT 1024
#define BB 8
#define L  24
#define NU 13    // u_0..u_12
#define NW 12    // w_0..w_11
#define PAD 68   // 272B row pitch

__device__ __align__(16) float g_k[NF * L];

// ------------------------------------------------------------------
__global__ __launch_bounds__(512, 2) void ssm_phase1(const float* __restrict__ A,
                                                     const float* __restrict__ B,
                                                     const float* __restrict__ C)
{
    asm volatile("griddepcontrol.launch_dependents;" ::: "memory");

    const int f    = blockIdx.x;
    const int tid  = threadIdx.x;
    const int rowg = tid >> 3;           // 0..63: owns row rowg
    const int colg = tid & 7;            // 0..7 : owns cols 8colg..8colg+7
    const int lanebase = (rowg & 3) * 8; // lane of colg==0 in this row group

    __shared__ __align__(16) float Ab[64 * PAD];   // A_bar
    __shared__ __align__(16) float Vw[NW * PAD];   // w_i vectors
    __shared__ __align__(16) float u_sm[2][64];
    __shared__ __align__(16) float w_sm2[2][64];
    __shared__ __align__(16) float Bsm[64], Csm[64];
    __shared__ __align__(16) union USh {
        float rowp[2][2][64];                      // GJ pivot-row panel
        float Vu[NU * PAD];                        // u_j vectors (after GJ)
    } ush;
    float* const Vu = ush.Vu;

    if (tid < 64) {
        Bsm[tid] = B[f * 64 + tid];
        Csm[tid] = C[f * 64 + tid];
    }

    // ---- init W = M = I - A/2 (one row/thread, float4 loads) ----
    float w[8];
    {
        const float* Arow = A + (size_t)f * 4096 + rowg * 64 + 8 * colg;
        const float4 a0 = *(const float4*)(Arow);
        const float4 a1 = *(const float4*)(Arow + 4);
        const float av[8] = {a0.x, a0.y, a0.z, a0.w, a1.x, a1.y, a1.z, a1.w};
#pragma unroll
        for (int jj = 0; jj < 8; ++jj) {
            const int j = 8 * colg + jj;
            w[jj] = ((rowg == j) ? 1.0f : 0.0f) - 0.5f * av[jj];
        }
    }

    // ---- block-2 in-place Gauss-Jordan, 32 single-barrier stages ----
    // Stage s: pivot rows/cols {2s, 2s+1}. Col owner colg == s>>2, register
    // slots j0 = 2(s&3), j0+1. Pivot rows are lanes xor-8 apart in warp s>>1.
#pragma unroll
    for (int s = 0; s < 32; ++s) {
        const int pb = s & 1;
        const int cp = s >> 2;
        const int j0 = 2 * (s & 3);
        const unsigned FM = 0xffffffffu;

        // own row's pivot-column values (pre-update)
        const float F0 = __shfl_sync(FM, w[j0],     lanebase + cp);
        const float F1 = __shfl_sync(FM, w[j0 + 1], lanebase + cp);

        const bool isPiv = (rowg == 2 * s) || (rowg == 2 * s + 1);

        if ((tid >> 5) == (s >> 1)) {
            // pivot warp: lanes 16*(s&1) .. 16*(s&1)+15 hold rows 2s,2s+1
            const unsigned PM = 0xFFFFu << (16 * (s & 1));
            if (isPiv) {
                const int g = rowg & 1;  // 0: row 2s, 1: row 2s+1
                const float xF0 = __shfl_xor_sync(PM, F0, 8);
                const float xF1 = __shfl_xor_sync(PM, F1, 8);
                const float pa = g ? xF0 : F0;
                const float pbv = g ? xF1 : F1;
                const float pc = g ? F0 : xF0;
                const float pd = g ? F1 : xF1;
                const float rdet = 1.0f / (pa * pd - pbv * pc);
                const float i00 =  pd * rdet, i01 = -pbv * rdet;
                const float i10 = -pc * rdet, i11 =  pa * rdet;
                // identity pre-write into pivot slots (augmented in place)
                if (colg == cp) {
                    w[j0]     = g ? 0.f : 1.f;
                    w[j0 + 1] = g ? 1.f : 0.f;
                }
                const float cOwn = g ? i11 : i00;   // coeff on own row
                const float cOth = g ? i10 : i01;   // coeff on partner row
                float r[8];
#pragma unroll
                for (int jj = 0; jj < 8; ++jj) {
                    const float o = __shfl_xor_sync(PM, w[jj], 8);
                    r[jj] = cOwn * w[jj] + cOth * o;
                    w[jj] = r[jj];
                }
                *(float4*)&ush.rowp[pb][g][8 * colg]     = make_float4(r[0], r[1], r[2], r[3]);
                *(float4*)&ush.rowp[pb][g][8 * colg + 4] = make_float4(r[4], r[5], r[6], r[7]);
            }
        }
        __syncthreads();

        // rank-2 elimination (non-pivot rows), pivot slots pre-zeroed
        if (!isPiv) {
            if (colg == cp) { w[j0] = 0.f; w[j0 + 1] = 0.f; }
            const float4 p0a = *(const float4*)&ush.rowp[pb][0][8 * colg];
            const float4 p0b = *(const float4*)&ush.rowp[pb][0][8 * colg + 4];
            const float4 p1a = *(const float4*)&ush.rowp[pb][1][8 * colg];
            const float4 p1b = *(const float4*)&ush.rowp[pb][1][8 * colg + 4];
            const float rp0[8] = {p0a.x, p0a.y, p0a.z, p0a.w, p0b.x, p0b.y, p0b.z, p0b.w};
            const float rp1[8] = {p1a.x, p1a.y, p1a.z, p1a.w, p1b.x, p1b.y, p1b.z, p1b.w};
#pragma unroll
            for (int jj = 0; jj < 8; ++jj)
                w[jj] -= F0 * rp0[jj] + F1 * rp1[jj];
        }
    }

    // ---- A_bar = 2*Minv - I -> smem (float4 stores) ----
    {
        float v[8];
#pragma unroll
        for (int jj = 0; jj < 8; ++jj) {
            const int j = 8 * colg + jj;
            v[jj] = 2.0f * w[jj] - ((rowg == j) ? 1.0f : 0.0f);
        }
        *(float4*)&Ab[rowg * PAD + 8 * colg]     = make_float4(v[0], v[1], v[2], v[3]);
        *(float4*)&Ab[rowg * PAD + 8 * colg + 4] = make_float4(v[4], v[5], v[6], v[7]);
    }
    __syncthreads();

    // ---- two concurrent 128-thread chains (a[32], named barriers) ----
    if (tid < 128) {
        // u-chain: u_0 = 0.5(A_bar B + B); u_j = A_bar u_{j-1}
        const int row = tid >> 1, half = tid & 1;
        float a[32];
#pragma unroll
        for (int q = 0; q < 32; ++q) a[q] = Ab[row * PAD + 32 * half + q];
        {
            float s0 = 0.f, s1 = 0.f, s2 = 0.f, s3 = 0.f;
#pragma unroll
            for (int q = 0; q < 8; ++q) {
                s0 += a[4 * q + 0] * Bsm[32 * half + 4 * q + 0];
                s1 += a[4 * q + 1] * Bsm[32 * half + 4 * q + 1];
                s2 += a[4 * q + 2] * Bsm[32 * half + 4 * q + 2];
                s3 += a[4 * q + 3] * Bsm[32 * half + 4 * q + 3];
            }
            float acc = (s0 + s1) + (s2 + s3);
            acc += __shfl_xor_sync(0xffffffffu, acc, 1);
            if (half == 0) {
                const float v = 0.5f * (acc + Bsm[row]);
                u_sm[0][row] = v;
                Vu[0 * PAD + row] = v;
            }
        }
        asm volatile("bar.sync 1, 128;" ::: "memory");
        for (int j = 1; j < NU; ++j) {
            const float4* vp = (const float4*)&u_sm[(j + 1) & 1][32 * half];
            float s0 = 0.f, s1 = 0.f, s2 = 0.f, s3 = 0.f;
#pragma unroll
            for (int q = 0; q < 8; ++q) {
                const float4 vv = vp[q];
                s0 += a[4 * q + 0] * vv.x;
                s1 += a[4 * q + 1] * vv.y;
                s2 += a[4 * q + 2] * vv.z;
                s3 += a[4 * q + 3] * vv.w;
            }
            float acc = (s0 + s1) + (s2 + s3);
            acc += __shfl_xor_sync(0xffffffffu, acc, 1);
            if (half == 0) {
                u_sm[j & 1][row] = acc;
                Vu[j * PAD + row] = acc;
            }
            asm volatile("bar.sync 1, 128;" ::: "memory");
        }
    } else if (tid < 256) {
        // w-chain: w_0 = C^T; w_i = A_bar^T w_{i-1}
        const int t2 = tid - 128;
        const int row = t2 >> 1, half = t2 & 1;
        float a[32];
#pragma unroll
        for (int q = 0; q < 32; ++q) a[q] = Ab[(32 * half + q) * PAD + row];
        if (half == 0) {
            w_sm2[0][row] = Csm[row];
            Vw[0 * PAD + row] = Csm[row];
        }
        asm volatile("bar.sync 2, 128;" ::: "memory");
        for (int i = 1; i < NW; ++i) {
            const float4* vp = (const float4*)&w_sm2[(i + 1) & 1][32 * half];
            float s0 = 0.f, s1 = 0.f, s2 = 0.f, s3 = 0.f;
#pragma unroll
            for (int q = 0; q < 8; ++q) {
                const float4 vv = vp[q];
                s0 += a[4 * q + 0] * vv.x;
                s1 += a[4 * q + 1] * vv.y;
                s2 += a[4 * q + 2] * vv.z;
                s3 += a[4 * q + 3] * vv.w;
            }
            float acc = (s0 + s1) + (s2 + s3);
            acc += __shfl_xor_sync(0xffffffffu, acc, 1);
            if (half == 0) {
                w_sm2[i & 1][row] = acc;
                Vw[i * PAD + row] = acc;
            }
            asm volatile("bar.sync 2, 128;" ::: "memory");
        }
    }
    __syncthreads();

    // ---- k_tau = w_i . u_{tau-i},  i = min(tau, NW-1), j = tau-i ----
    if (tid < 4 * L) {
        const int tau = tid >> 2, part = tid & 3;
        const int i = (tau < NW) ? tau : (NW - 1);
        const int j = tau - i;
        const float* wv = &Vw[i * PAD + 16 * part];
        const float* uv = &Vu[j * PAD + 16 * part];
        float s0 = 0.f, s1 = 0.f, s2 = 0.f, s3 = 0.f;
#pragma unroll
        for (int q = 0; q < 16; q += 4) {
            s0 += wv[q + 0] * uv[q + 0];
            s1 += wv[q + 1] * uv[q + 1];
            s2 += wv[q + 2] * uv[q + 2];
            s3 += wv[q + 3] * uv[q + 3];
        }
        float acc = (s0 + s1) + (s2 + s3);
        acc += __shfl_xor_sync(0xffffffffu, acc, 1);
        acc += __shfl_xor_sync(0xffffffffu, acc, 2);
        if (part == 0) g_k[f * L + tau] = acc;
    }
}

// ------------------------------------------------------------------
// Phase 2: causal FIR convolution (L=24). PDL: stage x first, then wait
// for phase1's g_k, then load taps and compute.
// ------------------------------------------------------------------
__global__ __launch_bounds__(128) void ssm_phase2(const float* __restrict__ x,
                                                  float* __restrict__ out)
{
    const int bf  = blockIdx.x;
    const int f   = bf & (NF - 1);
    const int tid = threadIdx.x;

    __shared__ float4 su4[(L + TT) / 4];
    __shared__ float4 k4[L / 4];

    const float4* x4 = (const float4*)(x + (size_t)bf * TT);
    const float4 z4 = make_float4(0.f, 0.f, 0.f, 0.f);
    for (int idx = tid; idx < (L + TT) / 4; idx += 128)
        su4[idx] = (idx < L / 4) ? z4 : x4[idx - L / 4];

    asm volatile("griddepcontrol.wait;" ::: "memory");

    if (tid < L / 4) k4[tid] = ((const float4*)(g_k + f * L))[tid];
    __syncthreads();

    const int base = tid * 8;

    float cbuf[16];
#pragma unroll
    for (int q = 0; q < 4; ++q) {
        const float4 v = su4[(L + base - 8) / 4 + q];
        cbuf[(4 * q - 8) & 15] = v.x;
        cbuf[(4 * q - 7) & 15] = v.y;
        cbuf[(4 * q - 6) & 15] = v.z;
        cbuf[(4 * q - 5) & 15] = v.w;
    }

    float y[8];
#pragma unroll
    for (int j = 0; j < 8; ++j) y[j] = 0.f;

#pragma unroll
    for (int blk = 0; blk < L / 4; ++blk) {
        const float4 kv = k4[blk];
        const float kk[4] = {kv.x, kv.y, kv.z, kv.w};
#pragma unroll
        for (int t = 0; t < 4; ++t) {
            const int tau = 4 * blk + t;
#pragma unroll
            for (int j = 0; j < 8; ++j)
                y[j] += kk[t] * cbuf[(j - tau) & 15];
        }
        if (blk <= (L - 12) / 4) {
            const float4 v = su4[(L + base - 4 * blk - 12) / 4];
            cbuf[(-4 * blk - 12) & 15] = v.x;
            cbuf[(-4 * blk - 11) & 15] = v.y;
            cbuf[(-4 * blk - 10) & 15] = v.z;
            cbuf[(-4 * blk -  9) & 15] = v.w;
        }
    }

    float4* o4 = (float4*)(out + (size_t)bf * TT + base);
    o4[0] = make_float4(y[0], y[1], y[2], y[3]);
    o4[1] = make_float4(y[4], y[5], y[6], y[7]);
}

// ------------------------------------------------------------------
extern "C" void kernel_launch(void* const* d_in, const int* in_sizes, int n_in,
                              void* d_out, int out_size)
{
    const float* x = (const float*)d_in[0];  // (8,256,1024)
    const float* A = (const float*)d_in[1];  // (256,64,64)
    const float* B = (const float*)d_in[2];  // (256,64,1)
    const float* C = (const float*)d_in[3];  // (256,1,64)
    float* out = (float*)d_out;              // (8,256,1024) f32

    ssm_phase1<<<NF, 512>>>(A, B, C);

    cudaLaunchConfig_t cfg = {};
    cfg.gridDim  = dim3(BB * NF, 1, 1);
    cfg.blockDim = dim3(128, 1, 1);
    cfg.dynamicSmemBytes = 0;
    cudaLaunchAttribute attrs[1];
    attrs[0].id = cudaLaunchAttributeProgrammaticStreamSerialization;
    attrs[0].val.programmaticStreamSerializationAllowed = 1;
    cfg.attrs = attrs;
    cfg.numAttrs = 1;
    cudaLaunchKernelEx(&cfg, ssm_phase2, x, out);
}